// round 3
// baseline (speedup 1.0000x reference)
#include <cuda_runtime.h>
#include <cstdint>

#define B_      8
#define AT_     96
#define NBR_    512
#define NANG_   125
#define NF_     128
#define NB_     128
#define ATOMS_  (B_*AT_)      // 768
#define CHUNK_  64
#define NCHUNK_ (NBR_/CHUNK_) // 8
#define PITCH_  132           // 132 mod 32 == 4 -> conflict-free fragment LDS
#define STF4_   2000          // 64*125/4 float4 per chunk

// shared memory layout (u32 units)
#define SM_ST   0                       // linear T staging: 8000 data + 64 zero tail
#define SM_H    8064                    // H tile, pitched tf32 (64 x PITCH_)
#define SM_TF   (SM_H + CHUNK_*PITCH_)  // W_triple tile, pitched f32
#define SM_FX   (SM_TF + CHUNK_*PITCH_)
// extras: b1s[128] b2s[128] js[64] ks[64] ms[64] aggs[256] t1s[128] = 832
#define SMEM_U32   (SM_FX + 832)
#define SMEM_BYTES (SMEM_U32*4)         // 103168 bytes -> 2 CTAs/SM

__device__ float    g_y[ATOMS_ * NF_];     // scratch: y = x @ Win
__device__ uint32_t g_W1t[128 * 128];      // W1 as tf32, zero rows 125..127
__device__ uint32_t g_W2t[128 * 128];      // W2 as tf32

__device__ __forceinline__ uint32_t f2tf32(float x) {
    uint32_t u; asm("cvt.rna.tf32.f32 %0, %1;" : "=r"(u) : "f"(x)); return u;
}

__device__ __forceinline__ float sspf(float x) {
    return fmaxf(x, 0.f) + __logf(1.f + __expf(-fabsf(x))) - 0.6931471805599453f;
}

__device__ __forceinline__ void mma_tf32(float c[4], const uint32_t a[4], const uint32_t b[2]) {
    asm volatile(
        "mma.sync.aligned.m16n8k8.row.col.f32.tf32.tf32.f32 "
        "{%0,%1,%2,%3}, {%4,%5,%6,%7}, {%8,%9}, {%0,%1,%2,%3};"
        : "+f"(c[0]), "+f"(c[1]), "+f"(c[2]), "+f"(c[3])
        : "r"(a[0]), "r"(a[1]), "r"(a[2]), "r"(a[3]), "r"(b[0]), "r"(b[1]));
}

__device__ __forceinline__ void cp_async16(uint32_t saddr, const void* gptr) {
    asm volatile("cp.async.cg.shared.global [%0], [%1], 16;"
                 :: "r"(saddr), "l"(gptr));
}
__device__ __forceinline__ void cp_commit() {
    asm volatile("cp.async.commit_group;");
}
__device__ __forceinline__ void cp_wait0() {
    asm volatile("cp.async.wait_group 0;" ::: "memory");
}

// ---------------------------------------------------------------------------
// Prep kernel: y = x @ Win (blocks 0..767) and W1/W2 tf32 convert (768..1023)
// ---------------------------------------------------------------------------
__global__ void __launch_bounds__(128)
prep_kernel(const float* __restrict__ x, const float* __restrict__ Win,
            const float* __restrict__ W1, const float* __restrict__ W2)
{
    const int bid = blockIdx.x, t = threadIdx.x;
    if (bid < ATOMS_) {
        __shared__ float xs[NB_];
        xs[t] = x[bid*NB_ + t];
        __syncthreads();
        float acc = 0.f;
        #pragma unroll 16
        for (int gg = 0; gg < NB_; ++gg)
            acc = fmaf(xs[gg], Win[gg*NF_ + t], acc);
        g_y[bid*NF_ + t] = acc;
    } else {
        int r = bid - ATOMS_;          // 0..255
        if (r < 128) {
            g_W1t[r*128 + t] = (r < NANG_) ? f2tf32(W1[r*128 + t]) : 0u;
        } else {
            int rr = r - 128;
            g_W2t[rr*128 + t] = f2tf32(W2[rr*128 + t]);
        }
    }
}

// ---------------------------------------------------------------------------
// Fused main kernel: one CTA per atom
// ---------------------------------------------------------------------------
__global__ void __launch_bounds__(256, 2)
fused_kernel(const float* __restrict__ triple,
             const int*   __restrict__ nj, const int* __restrict__ nk,
             const float* __restrict__ mask,
             const float* __restrict__ b1, const float* __restrict__ b2,
             const float* __restrict__ Wf2, const float* __restrict__ bf2,
             const float* __restrict__ Wd,  const float* __restrict__ bd,
             const float* __restrict__ x,   float* __restrict__ out)
{
    extern __shared__ uint32_t sm[];
    uint32_t* StU = sm + SM_ST;                       // linear T staging (tf32 after convert)
    float4*   Stf4 = reinterpret_cast<float4*>(StU);
    uint4*    Stu4 = reinterpret_cast<uint4*>(StU);
    uint32_t* Hs  = sm + SM_H;
    float*    Tf  = reinterpret_cast<float*>(sm + SM_TF);
    float*    fx  = reinterpret_cast<float*>(sm + SM_FX);
    float* b1s = fx;
    float* b2s = fx + 128;
    int*   js  = reinterpret_cast<int*>(fx + 256);
    int*   ks  = js + 64;
    float* ms  = fx + 256 + 128;
    float* aggs = ms + 64;                // 256
    float* t1s  = aggs + 256;             // 128

    const int t    = threadIdx.x;
    const int atom = blockIdx.x;
    const int bidx = atom / AT_;
    const int lane = t & 31;
    const int warp = t >> 5;
    const int g  = lane >> 2;      // groupID
    const int c  = lane & 3;       // thread-in-group
    const int mg = warp >> 2;      // 0..1  (M 32-row group)
    const int ng = warp & 3;       // 0..3  (N 32-col group)

    if (t < 128) { b1s[t] = b1[t]; b2s[t] = b2[t]; }
    if (t < 64)  StU[8000 + t] = 0u;      // zero tail (GEMM1 A k-pad overreach)

    const size_t tb = (size_t)atom * NBR_ * NANG_;
    const int    nb = atom * NBR_;
    const uint32_t stBase = (uint32_t)__cvta_generic_to_shared(StU);

    // prefetch chunk 0
    {
        const float4* src = reinterpret_cast<const float4*>(triple + tb);
        #pragma unroll
        for (int i = 0; i < 8; ++i) {
            int idx = t + i*256;
            if (idx < STF4_) cp_async16(stBase + idx*16, src + idx);
        }
        cp_commit();
    }

    float aggAcc = 0.f;
    const int f    = t & 127;
    const int half = t >> 7;
    const float* yb = g_y + bidx * AT_ * NF_;

    for (int ch = 0; ch < NCHUNK_; ++ch) {
        cp_wait0();
        __syncthreads();   // staging ready for all; prev EW done with Tf/Hs

        if (t < CHUNK_) {
            js[t] = nj[nb + ch*CHUNK_ + t];
            ks[t] = nk[nb + ch*CHUNK_ + t];
            ms[t] = mask[nb + ch*CHUNK_ + t];
        }
        // in-place RNA tf32 convert of staged chunk
        #pragma unroll
        for (int i = 0; i < 8; ++i) {
            int idx = t + i*256;
            if (idx < STF4_) {
                float4 v = Stf4[idx];
                uint4 u;
                u.x = f2tf32(v.x); u.y = f2tf32(v.y);
                u.z = f2tf32(v.z); u.w = f2tf32(v.w);
                Stu4[idx] = u;
            }
        }
        __syncthreads();

        // ================= GEMM1: H = ssp(T @ W1 + b1) =================
        {
            float acc[2][4][4];
            #pragma unroll
            for (int mt=0;mt<2;mt++)
                #pragma unroll
                for (int nt=0;nt<4;nt++)
                    #pragma unroll
                    for (int i=0;i<4;i++) acc[mt][nt][i]=0.f;
            #pragma unroll
            for (int kk = 0; kk < 16; ++kk) {
                const int k0 = kk*8;
                uint32_t a[2][4], bb[4][2];
                #pragma unroll
                for (int mt = 0; mt < 2; ++mt) {
                    int r0 = (mg*32 + mt*16 + g)*125;
                    a[mt][0]=StU[r0       + k0 + c    ];
                    a[mt][1]=StU[r0 + 1000 + k0 + c    ];   // +8 rows
                    a[mt][2]=StU[r0       + k0 + c + 4];
                    a[mt][3]=StU[r0 + 1000 + k0 + c + 4];
                }
                #pragma unroll
                for (int nt = 0; nt < 4; ++nt) {
                    int n0 = ng*32 + nt*8 + g;
                    bb[nt][0]=__ldg(&g_W1t[(k0+c  )*128 + n0]);
                    bb[nt][1]=__ldg(&g_W1t[(k0+c+4)*128 + n0]);
                }
                #pragma unroll
                for (int mt = 0; mt < 2; ++mt)
                    #pragma unroll
                    for (int nt = 0; nt < 4; ++nt)
                        mma_tf32(acc[mt][nt], a[mt], bb[nt]);
            }
            #pragma unroll
            for (int mt = 0; mt < 2; ++mt)
                #pragma unroll
                for (int nt = 0; nt < 4; ++nt)
                    #pragma unroll
                    for (int i = 0; i < 4; ++i) {
                        int row = mg*32 + mt*16 + g + ((i>>1)<<3);
                        int col = ng*32 + nt*8 + (c<<1) + (i&1);
                        float v = sspf(acc[mt][nt][i] + b1s[col]);
                        Hs[row*PITCH_ + col] = f2tf32(v);
                    }
        }
        __syncthreads();

        // staging free -> prefetch next chunk (overlaps GEMM2 + elementwise)
        if (ch + 1 < NCHUNK_) {
            const float4* src = reinterpret_cast<const float4*>(
                triple + tb + (size_t)(ch+1)*CHUNK_*NANG_);
            #pragma unroll
            for (int i = 0; i < 8; ++i) {
                int idx = t + i*256;
                if (idx < STF4_) cp_async16(stBase + idx*16, src + idx);
            }
        }
        cp_commit();

        // ================= GEMM2: Wt = H @ W2 + b2  (-> Tf) =================
        {
            float acc[2][4][4];
            #pragma unroll
            for (int mt=0;mt<2;mt++)
                #pragma unroll
                for (int nt=0;nt<4;nt++)
                    #pragma unroll
                    for (int i=0;i<4;i++) acc[mt][nt][i]=0.f;
            #pragma unroll
            for (int kk = 0; kk < 16; ++kk) {
                const int k0 = kk*8;
                uint32_t a[2][4], bb[4][2];
                #pragma unroll
                for (int mt = 0; mt < 2; ++mt) {
                    int r0 = mg*32 + mt*16 + g;
                    a[mt][0]=Hs[ r0   *PITCH_ + k0 + c    ];
                    a[mt][1]=Hs[(r0+8)*PITCH_ + k0 + c    ];
                    a[mt][2]=Hs[ r0   *PITCH_ + k0 + c + 4];
                    a[mt][3]=Hs[(r0+8)*PITCH_ + k0 + c + 4];
                }
                #pragma unroll
                for (int nt = 0; nt < 4; ++nt) {
                    int n0 = ng*32 + nt*8 + g;
                    bb[nt][0]=__ldg(&g_W2t[(k0+c  )*128 + n0]);
                    bb[nt][1]=__ldg(&g_W2t[(k0+c+4)*128 + n0]);
                }
                #pragma unroll
                for (int mt = 0; mt < 2; ++mt)
                    #pragma unroll
                    for (int nt = 0; nt < 4; ++nt)
                        mma_tf32(acc[mt][nt], a[mt], bb[nt]);
            }
            #pragma unroll
            for (int mt = 0; mt < 2; ++mt)
                #pragma unroll
                for (int nt = 0; nt < 4; ++nt)
                    #pragma unroll
                    for (int i = 0; i < 4; ++i) {
                        int row = mg*32 + mt*16 + g + ((i>>1)<<3);
                        int col = ng*32 + nt*8 + (c<<1) + (i&1);
                        Tf[row*PITCH_ + col] = acc[mt][nt][i] + b2s[col];
                    }
        }
        __syncthreads();

        // ===== elementwise: agg[f] += mask * y_j[f] * y_k[f] * Wt[r][f] =====
        #pragma unroll 8
        for (int r = half; r < CHUNK_; r += 2) {
            int jrow = js[r], krow = ks[r];
            float m  = ms[r];
            float yj = __ldg(&yb[jrow*NF_ + f]);
            float yk = __ldg(&yb[krow*NF_ + f]);
            float wt = Tf[r*PITCH_ + f];
            aggAcc = fmaf(m * yj * yk, wt, aggAcc);
        }
    }

    // ===== per-atom epilogue: v = ssp(agg@Wf2+bf2) @ Wd + bd; out = x + v =====
    aggs[half*128 + f] = aggAcc;
    __syncthreads();
    if (t < 128) aggs[t] = aggs[t] + aggs[128 + t];
    __syncthreads();
    if (t < 128) {
        float a1 = bf2[t];
        #pragma unroll 8
        for (int gg = 0; gg < 128; ++gg)
            a1 = fmaf(aggs[gg], Wf2[gg*NB_ + t], a1);
        t1s[t] = sspf(a1);
    }
    __syncthreads();
    if (t < 128) {
        float a2 = bd[t];
        #pragma unroll 8
        for (int gg = 0; gg < 128; ++gg)
            a2 = fmaf(t1s[gg], Wd[gg*NB_ + t], a2);
        out[atom*NB_ + t] = x[atom*NB_ + t] + a2;
    }
}

// ---------------------------------------------------------------------------
extern "C" void kernel_launch(void* const* d_in, const int* in_sizes, int n_in,
                              void* d_out, int out_size)
{
    const float* x      = (const float*)d_in[0];
    const float* triple = (const float*)d_in[1];
    const int*   nj     = (const int*)  d_in[2];
    const int*   nk     = (const int*)  d_in[3];
    const float* mask   = (const float*)d_in[4];
    const float* W1     = (const float*)d_in[5];
    const float* b1     = (const float*)d_in[6];
    const float* W2     = (const float*)d_in[7];
    const float* b2     = (const float*)d_in[8];
    const float* Win    = (const float*)d_in[9];
    const float* Wf2    = (const float*)d_in[10];
    const float* bf2    = (const float*)d_in[11];
    const float* Wd     = (const float*)d_in[12];
    const float* bd     = (const float*)d_in[13];
    float* out = (float*)d_out;

    cudaFuncSetAttribute(fused_kernel,
                         cudaFuncAttributeMaxDynamicSharedMemorySize, SMEM_BYTES);

    prep_kernel<<<ATOMS_ + 256, 128>>>(x, Win, W1, W2);
    fused_kernel<<<ATOMS_, 256, SMEM_BYTES>>>(triple, nj, nk, mask,
                                              b1, b2,
                                              Wf2, bf2, Wd, bd, x, out);
}

// round 5
// speedup vs baseline: 1.6910x; 1.6910x over previous
#include <cuda_runtime.h>
#include <cstdint>

#define B_      8
#define AT_     96
#define NBR_    512
#define NANG_   125
#define NF_     128
#define NB_     128
#define ATOMS_  (B_*AT_)      // 768
#define CHUNK_  64
#define NCHUNK_ (NBR_/CHUNK_) // 8
#define PITCH_  132           // %32==4 -> conflict-free fragment LDS; %4==0 for LDS.128

// smem layout (u32 units)
#define SM_T    0                       // T tile / Wt output (64 x PITCH_)
#define SM_H    (CHUNK_*PITCH_)         // H tile (64 x PITCH_)
#define SM_EX   (2*CHUNK_*PITCH_)
// EX floats: b1s[128] b2s[128] js[64] ks[64] ms[64] aggp[1024] aggs[128] t1s[128] = 1728
#define SMEM_U32   (SM_EX + 1728)
#define SMEM_BYTES (SMEM_U32*4)         // 74,496 B -> 2 CTAs/SM, ~79KB L1 left

__device__ float g_y[ATOMS_ * NF_];                 // y = x @ Win
// packed B fragments: uint4 idx = ((ng*8+p)*4+nt)*32+lane,
// words w=0..3 hold tf32 W[k][n] with k=16p+4w+c, n=ng*32+nt*8+g  (lane=g*4+c)
__device__ __align__(16) uint32_t g_W1p[4096*4];
__device__ __align__(16) uint32_t g_W2p[4096*4];

__device__ __forceinline__ uint32_t f2tf32(float x) {
    uint32_t u; asm("cvt.rna.tf32.f32 %0, %1;" : "=r"(u) : "f"(x)); return u;
}
__device__ __forceinline__ float sspf(float x) {
    return fmaxf(x, 0.f) + __logf(1.f + __expf(-fabsf(x))) - 0.6931471805599453f;
}
__device__ __forceinline__ void mma_tf32(float c[4], const uint32_t a[4], const uint32_t b[2]) {
    asm volatile(
        "mma.sync.aligned.m16n8k8.row.col.f32.tf32.tf32.f32 "
        "{%0,%1,%2,%3}, {%4,%5,%6,%7}, {%8,%9}, {%0,%1,%2,%3};"
        : "+f"(c[0]), "+f"(c[1]), "+f"(c[2]), "+f"(c[3])
        : "r"(a[0]), "r"(a[1]), "r"(a[2]), "r"(a[3]), "r"(b[0]), "r"(b[1]));
}

// ---------------------------------------------------------------------------
// Prep: y = x@Win (blocks 0..767); B-fragment packing (blocks 768..831)
// ---------------------------------------------------------------------------
__global__ void __launch_bounds__(128)
prep_kernel(const float* __restrict__ x, const float* __restrict__ Win,
            const float* __restrict__ W1, const float* __restrict__ W2)
{
    const int bid = blockIdx.x, t = threadIdx.x;
    if (bid < ATOMS_) {
        __shared__ float xs[NB_];
        xs[t] = x[bid*NB_ + t];
        __syncthreads();
        float acc = 0.f;
        #pragma unroll 16
        for (int gg = 0; gg < NB_; ++gg)
            acc = fmaf(xs[gg], Win[gg*NF_ + t], acc);
        g_y[bid*NF_ + t] = acc;
    } else {
        int e = (bid - ATOMS_)*128 + t;          // 0..8191
        const float* W   = (e < 4096) ? W1 : W2;
        const int    kmax = (e < 4096) ? NANG_ : 128;
        uint32_t*    dst = (e < 4096) ? g_W1p : g_W2p;
        int e2 = e & 4095;
        int lane = e2 & 31, nt = (e2>>5)&3, p = (e2>>7)&7, ng = e2>>10;
        int g = lane>>2, c = lane&3, n = ng*32 + nt*8 + g;
        uint4 v;
        {
            int k0 = 16*p + c;
            v.x = (k0      < kmax) ? f2tf32(W[(k0     )*128 + n]) : 0u;
            v.y = (k0 + 4  < kmax) ? f2tf32(W[(k0 +  4)*128 + n]) : 0u;
            v.z = (k0 + 8  < kmax) ? f2tf32(W[(k0 +  8)*128 + n]) : 0u;
            v.w = (k0 + 12 < kmax) ? f2tf32(W[(k0 + 12)*128 + n]) : 0u;
        }
        reinterpret_cast<uint4*>(dst)[e2] = v;
    }
}

// ---------------------------------------------------------------------------
// Fused main kernel: one CTA per atom
// ---------------------------------------------------------------------------
__global__ void __launch_bounds__(256, 2)
fused_kernel(const float* __restrict__ triple,
             const int*   __restrict__ nj, const int* __restrict__ nk,
             const float* __restrict__ mask,
             const float* __restrict__ b1, const float* __restrict__ b2,
             const float* __restrict__ Wf2, const float* __restrict__ bf2,
             const float* __restrict__ Wd,  const float* __restrict__ bd,
             const float* __restrict__ x,   float* __restrict__ out)
{
    extern __shared__ uint32_t sm[];
    uint32_t* Ts  = sm + SM_T;
    uint32_t* Hs  = sm + SM_H;
    float*    Tf  = reinterpret_cast<float*>(Ts);   // Wt view (f32)
    float*    ex  = reinterpret_cast<float*>(sm + SM_EX);
    float* b1s = ex;
    float* b2s = ex + 128;
    int*   js  = reinterpret_cast<int*>(ex + 256);
    int*   ks  = js + 64;
    float* ms  = ex + 256 + 128;
    float* aggp = ms + 64;                // 1024 (8 rq x 128 f)
    float* aggs = aggp + 1024;            // 128
    float* t1s  = aggs + 128;             // 128

    const int t    = threadIdx.x;
    const int atom = blockIdx.x;
    const int bidx = atom / AT_;
    const int lane = t & 31;
    const int warp = t >> 5;
    const int g  = lane >> 2;
    const int c  = lane & 3;
    const int mg = warp >> 2;      // 0..1
    const int ng = warp & 3;       // 0..3

    if (t < 128) { b1s[t] = b1[t]; b2s[t] = b2[t]; }

    const int nb = atom * NBR_;
    const float* yb = g_y + bidx * AT_ * NF_;
    const uint4* W1p4 = reinterpret_cast<const uint4*>(g_W1p);
    const uint4* W2p4 = reinterpret_cast<const uint4*>(g_W2p);

    // EW state: thread owns float4 column group cg, rows rq*8..rq*8+7
    const int cg = t & 31;
    const int rq = t >> 5;
    float4 acc4 = make_float4(0.f, 0.f, 0.f, 0.f);

    for (int ch = 0; ch < NCHUNK_; ++ch) {
        __syncthreads();   // prev EW done with Tf before overwrite

        // ---- T scatter: warp w -> rows w*8..w*8+7; k = lane + 32i ----
        {
            const float* tbase = triple + ((size_t)nb + (size_t)ch*CHUNK_ + warp*8)*NANG_;
            #pragma unroll
            for (int i = 0; i < 8; ++i) {
                const float* trow = tbase + i*NANG_;
                uint32_t* srow = &Ts[(warp*8 + i)*PITCH_];
                #pragma unroll
                for (int q = 0; q < 4; ++q) {
                    int k = lane + q*32;
                    float v = (k < NANG_) ? __ldg(trow + k) : 0.f;
                    srow[k] = f2tf32(v);
                }
            }
        }
        if (t < CHUNK_) {
            js[t] = nj[nb + ch*CHUNK_ + t];
            ks[t] = nk[nb + ch*CHUNK_ + t];
            ms[t] = mask[nb + ch*CHUNK_ + t];
        }
        __syncthreads();

        // ================= GEMM1: H = ssp(T @ W1 + b1) =================
        {
            float acc[2][4][4];
            #pragma unroll
            for (int mt=0;mt<2;mt++)
                #pragma unroll
                for (int nt=0;nt<4;nt++)
                    #pragma unroll
                    for (int i=0;i<4;i++) acc[mt][nt][i]=0.f;
            #pragma unroll
            for (int p = 0; p < 8; ++p) {
                uint4 B4[4];
                #pragma unroll
                for (int nt = 0; nt < 4; ++nt)
                    B4[nt] = __ldg(&W1p4[((ng*8 + p)*4 + nt)*32 + lane]);
                #pragma unroll
                for (int sub = 0; sub < 2; ++sub) {
                    const int k0 = p*16 + sub*8;
                    uint32_t a[2][4];
                    #pragma unroll
                    for (int mt = 0; mt < 2; ++mt) {
                        int r0 = (mg*32 + mt*16 + g)*PITCH_;
                        a[mt][0]=Ts[r0            + k0 + c    ];
                        a[mt][1]=Ts[r0 + 8*PITCH_ + k0 + c    ];
                        a[mt][2]=Ts[r0            + k0 + c + 4];
                        a[mt][3]=Ts[r0 + 8*PITCH_ + k0 + c + 4];
                    }
                    #pragma unroll
                    for (int mt = 0; mt < 2; ++mt)
                        #pragma unroll
                        for (int nt = 0; nt < 4; ++nt) {
                            uint32_t bb[2];
                            bb[0] = sub ? B4[nt].z : B4[nt].x;
                            bb[1] = sub ? B4[nt].w : B4[nt].y;
                            mma_tf32(acc[mt][nt], a[mt], bb);
                        }
                }
            }
            #pragma unroll
            for (int mt = 0; mt < 2; ++mt)
                #pragma unroll
                for (int nt = 0; nt < 4; ++nt)
                    #pragma unroll
                    for (int i = 0; i < 4; ++i) {
                        int row = mg*32 + mt*16 + g + ((i>>1)<<3);
                        int col = ng*32 + nt*8 + (c<<1) + (i&1);
                        float v = sspf(acc[mt][nt][i] + b1s[col]);
                        Hs[row*PITCH_ + col] = f2tf32(v);
                    }
        }
        __syncthreads();   // Hs ready; Ts fragment reads complete

        // ================= GEMM2: Wt = H @ W2 + b2  (-> Ts region) =================
        {
            float acc[2][4][4];
            #pragma unroll
            for (int mt=0;mt<2;mt++)
                #pragma unroll
                for (int nt=0;nt<4;nt++)
                    #pragma unroll
                    for (int i=0;i<4;i++) acc[mt][nt][i]=0.f;
            #pragma unroll
            for (int p = 0; p < 8; ++p) {
                uint4 B4[4];
                #pragma unroll
                for (int nt = 0; nt < 4; ++nt)
                    B4[nt] = __ldg(&W2p4[((ng*8 + p)*4 + nt)*32 + lane]);
                #pragma unroll
                for (int sub = 0; sub < 2; ++sub) {
                    const int k0 = p*16 + sub*8;
                    uint32_t a[2][4];
                    #pragma unroll
                    for (int mt = 0; mt < 2; ++mt) {
                        int r0 = (mg*32 + mt*16 + g)*PITCH_;
                        a[mt][0]=Hs[r0            + k0 + c    ];
                        a[mt][1]=Hs[r0 + 8*PITCH_ + k0 + c    ];
                        a[mt][2]=Hs[r0            + k0 + c + 4];
                        a[mt][3]=Hs[r0 + 8*PITCH_ + k0 + c + 4];
                    }
                    #pragma unroll
                    for (int mt = 0; mt < 2; ++mt)
                        #pragma unroll
                        for (int nt = 0; nt < 4; ++nt) {
                            uint32_t bb[2];
                            bb[0] = sub ? B4[nt].z : B4[nt].x;
                            bb[1] = sub ? B4[nt].w : B4[nt].y;
                            mma_tf32(acc[mt][nt], a[mt], bb);
                        }
                }
            }
            #pragma unroll
            for (int mt = 0; mt < 2; ++mt)
                #pragma unroll
                for (int nt = 0; nt < 4; ++nt)
                    #pragma unroll
                    for (int i = 0; i < 4; ++i) {
                        int row = mg*32 + mt*16 + g + ((i>>1)<<3);
                        int col = ng*32 + nt*8 + (c<<1) + (i&1);
                        Tf[row*PITCH_ + col] = acc[mt][nt][i] + b2s[col];
                    }
        }
        __syncthreads();   // Wt complete

        // ===== elementwise (vectorized): acc4 += m*yj4*yk4*wt4 =====
        #pragma unroll
        for (int i = 0; i < 8; ++i) {
            int r = rq*8 + i;
            int jrow = js[r], krow = ks[r];
            float m  = ms[r];
            float4 yj = *reinterpret_cast<const float4*>(&yb[jrow*NF_ + cg*4]);
            float4 yk = *reinterpret_cast<const float4*>(&yb[krow*NF_ + cg*4]);
            float4 wt = *reinterpret_cast<const float4*>(&Tf[r*PITCH_ + cg*4]);
            acc4.x = fmaf(m * yj.x * yk.x, wt.x, acc4.x);
            acc4.y = fmaf(m * yj.y * yk.y, wt.y, acc4.y);
            acc4.z = fmaf(m * yj.z * yk.z, wt.z, acc4.z);
            acc4.w = fmaf(m * yj.w * yk.w, wt.w, acc4.w);
        }
    }

    // ===== reduce acc4 across rq groups, then per-atom epilogue =====
    *reinterpret_cast<float4*>(&aggp[(rq*32 + cg)*4]) = acc4;
    __syncthreads();
    if (t < 128) {
        float s = 0.f;
        #pragma unroll
        for (int r = 0; r < 8; ++r) s += aggp[r*128 + t];
        aggs[t] = s;
    }
    __syncthreads();
    if (t < 128) {
        float a1 = bf2[t];
        #pragma unroll 8
        for (int gg = 0; gg < 128; ++gg)
            a1 = fmaf(aggs[gg], Wf2[gg*NB_ + t], a1);
        t1s[t] = sspf(a1);
    }
    __syncthreads();
    if (t < 128) {
        float a2 = bd[t];
        #pragma unroll 8
        for (int gg = 0; gg < 128; ++gg)
            a2 = fmaf(t1s[gg], Wd[gg*NB_ + t], a2);
        out[atom*NB_ + t] = x[atom*NB_ + t] + a2;
    }
}

// ---------------------------------------------------------------------------
extern "C" void kernel_launch(void* const* d_in, const int* in_sizes, int n_in,
                              void* d_out, int out_size)
{
    const float* x      = (const float*)d_in[0];
    const float* triple = (const float*)d_in[1];
    const int*   nj     = (const int*)  d_in[2];
    const int*   nk     = (const int*)  d_in[3];
    const float* mask   = (const float*)d_in[4];
    const float* W1     = (const float*)d_in[5];
    const float* b1     = (const float*)d_in[6];
    const float* W2     = (const float*)d_in[7];
    const float* b2     = (const float*)d_in[8];
    const float* Win    = (const float*)d_in[9];
    const float* Wf2    = (const float*)d_in[10];
    const float* bf2    = (const float*)d_in[11];
    const float* Wd     = (const float*)d_in[12];
    const float* bd     = (const float*)d_in[13];
    float* out = (float*)d_out;

    cudaFuncSetAttribute(fused_kernel,
                         cudaFuncAttributeMaxDynamicSharedMemorySize, SMEM_BYTES);

    prep_kernel<<<ATOMS_ + 64, 128>>>(x, Win, W1, W2);
    fused_kernel<<<ATOMS_, 256, SMEM_BYTES>>>(triple, nj, nk, mask,
                                              b1, b2, Wf2, bf2, Wd, bd, x, out);
}

// round 6
// speedup vs baseline: 1.8006x; 1.0648x over previous
#include <cuda_runtime.h>
#include <cstdint>

#define B_      8
#define AT_     96
#define NBR_    512
#define NANG_   125
#define NF_     128
#define NB_     128
#define ATOMS_  (B_*AT_)      // 768
#define CHUNK_  64
#define NCHUNK_ (NBR_/CHUNK_) // 8
#define PITCH_  132           // %32==4 -> conflict-free fragment LDS; %4==0 for LDS.128

// smem layout (u32 units)
#define SM_T    0                       // T tile / Wt output (64 x PITCH_)
#define SM_H    (CHUNK_*PITCH_)         // H tile (64 x PITCH_)
#define SM_EX   (2*CHUNK_*PITCH_)
// EX floats: b1s[128] b2s[128] js[64] ks[64] ms[64] aggp[1024] aggs[128] t1s[128] = 1728
#define SMEM_U32   (SM_EX + 1728)
#define SMEM_BYTES (SMEM_U32*4)         // 74,496 B  (3 CTAs: 223.5KB < 227KB)

__device__ float g_y[ATOMS_ * NF_];                 // y = x @ Win
// packed B fragments: uint4 idx = ((ng*8+p)*4+nt)*32+lane,
// words w=0..3 hold tf32 W[k][n] with k=16p+4w+c, n=ng*32+nt*8+g  (lane=g*4+c)
__device__ __align__(16) uint32_t g_W1p[4096*4];
__device__ __align__(16) uint32_t g_W2p[4096*4];

__device__ __forceinline__ uint32_t f2tf32(float x) {
    uint32_t u; asm("cvt.rna.tf32.f32 %0, %1;" : "=r"(u) : "f"(x)); return u;
}
__device__ __forceinline__ float sspf(float x) {
    return fmaxf(x, 0.f) + __logf(1.f + __expf(-fabsf(x))) - 0.6931471805599453f;
}
__device__ __forceinline__ void mma_tf32(float c[4], const uint32_t a[4], const uint32_t b[2]) {
    asm volatile(
        "mma.sync.aligned.m16n8k8.row.col.f32.tf32.tf32.f32 "
        "{%0,%1,%2,%3}, {%4,%5,%6,%7}, {%8,%9}, {%0,%1,%2,%3};"
        : "+f"(c[0]), "+f"(c[1]), "+f"(c[2]), "+f"(c[3])
        : "r"(a[0]), "r"(a[1]), "r"(a[2]), "r"(a[3]), "r"(b[0]), "r"(b[1]));
}

// ---------------------------------------------------------------------------
// Prep: y = x@Win (blocks 0..767); B-fragment packing (blocks 768..831)
// ---------------------------------------------------------------------------
__global__ void __launch_bounds__(128)
prep_kernel(const float* __restrict__ x, const float* __restrict__ Win,
            const float* __restrict__ W1, const float* __restrict__ W2)
{
    const int bid = blockIdx.x, t = threadIdx.x;
    if (bid < ATOMS_) {
        __shared__ float xs[NB_];
        xs[t] = x[bid*NB_ + t];
        __syncthreads();
        float acc = 0.f;
        #pragma unroll 16
        for (int gg = 0; gg < NB_; ++gg)
            acc = fmaf(xs[gg], Win[gg*NF_ + t], acc);
        g_y[bid*NF_ + t] = acc;
    } else {
        int e = (bid - ATOMS_)*128 + t;          // 0..8191
        const float* W   = (e < 4096) ? W1 : W2;
        const int    kmax = (e < 4096) ? NANG_ : 128;
        uint32_t*    dst = (e < 4096) ? g_W1p : g_W2p;
        int e2 = e & 4095;
        int lane = e2 & 31, nt = (e2>>5)&3, p = (e2>>7)&7, ng = e2>>10;
        int g = lane>>2, c = lane&3, n = ng*32 + nt*8 + g;
        uint4 v;
        {
            int k0 = 16*p + c;
            v.x = (k0      < kmax) ? f2tf32(W[(k0     )*128 + n]) : 0u;
            v.y = (k0 + 4  < kmax) ? f2tf32(W[(k0 +  4)*128 + n]) : 0u;
            v.z = (k0 + 8  < kmax) ? f2tf32(W[(k0 +  8)*128 + n]) : 0u;
            v.w = (k0 + 12 < kmax) ? f2tf32(W[(k0 + 12)*128 + n]) : 0u;
        }
        reinterpret_cast<uint4*>(dst)[e2] = v;
    }
}

// ---------------------------------------------------------------------------
// Fused main kernel: one CTA per atom, 3 CTAs/SM target
// ---------------------------------------------------------------------------
__global__ void __launch_bounds__(256, 3)
fused_kernel(const float* __restrict__ triple,
             const int*   __restrict__ nj, const int* __restrict__ nk,
             const float* __restrict__ mask,
             const float* __restrict__ b1, const float* __restrict__ b2,
             const float* __restrict__ Wf2, const float* __restrict__ bf2,
             const float* __restrict__ Wd,  const float* __restrict__ bd,
             const float* __restrict__ x,   float* __restrict__ out)
{
    extern __shared__ uint32_t sm[];
    uint32_t* Ts  = sm + SM_T;
    uint32_t* Hs  = sm + SM_H;
    float*    Tf  = reinterpret_cast<float*>(Ts);   // Wt view (f32)
    float*    ex  = reinterpret_cast<float*>(sm + SM_EX);
    float* b1s = ex;
    float* b2s = ex + 128;
    int*   js  = reinterpret_cast<int*>(ex + 256);
    int*   ks  = js + 64;
    float* ms  = ex + 256 + 128;
    float* aggp = ms + 64;                // 1024 (8 rq x 128 f)
    float* aggs = aggp + 1024;            // 128
    float* t1s  = aggs + 128;             // 128

    const int t    = threadIdx.x;
    const int atom = blockIdx.x;
    const int bidx = atom / AT_;
    const int lane = t & 31;
    const int warp = t >> 5;
    const int g  = lane >> 2;
    const int c  = lane & 3;
    const int mg = warp >> 2;      // 0..1
    const int ng = warp & 3;       // 0..3

    if (t < 128) { b1s[t] = b1[t]; b2s[t] = b2[t]; }

    const int nb = atom * NBR_;
    const float* yb = g_y + bidx * AT_ * NF_;
    const uint4* W1p4 = reinterpret_cast<const uint4*>(g_W1p);
    const uint4* W2p4 = reinterpret_cast<const uint4*>(g_W2p);

    // EW state: thread owns float4 column group cg, rows rq*8..rq*8+7
    const int cg = t & 31;
    const int rq = t >> 5;
    float4 acc4 = make_float4(0.f, 0.f, 0.f, 0.f);

    for (int ch = 0; ch < NCHUNK_; ++ch) {
        __syncthreads();   // prev EW done with Tf before overwrite

        // ---- T scatter: warp w -> rows w*8..w*8+7; k = lane + 32i ----
        {
            const float* tbase = triple + ((size_t)nb + (size_t)ch*CHUNK_ + warp*8)*NANG_;
            #pragma unroll
            for (int i = 0; i < 8; ++i) {
                const float* trow = tbase + i*NANG_;
                uint32_t* srow = &Ts[(warp*8 + i)*PITCH_];
                #pragma unroll
                for (int q = 0; q < 4; ++q) {
                    int k = lane + q*32;
                    float v = (k < NANG_) ? __ldg(trow + k) : 0.f;
                    srow[k] = f2tf32(v);
                }
            }
        }
        if (t < CHUNK_) {
            js[t] = nj[nb + ch*CHUNK_ + t];
            ks[t] = nk[nb + ch*CHUNK_ + t];
            ms[t] = mask[nb + ch*CHUNK_ + t];
        }
        __syncthreads();

        // ================= GEMM1: H = ssp(T @ W1 + b1) =================
        {
            float acc[2][4][4];
            #pragma unroll
            for (int mt=0;mt<2;mt++)
                #pragma unroll
                for (int nt=0;nt<4;nt++)
                    #pragma unroll
                    for (int i=0;i<4;i++) acc[mt][nt][i]=0.f;
            #pragma unroll
            for (int p = 0; p < 8; ++p) {
                // hoist A fragments for both k-subs of this p (16 regs)
                uint32_t a[2][2][4];
                #pragma unroll
                for (int sub = 0; sub < 2; ++sub) {
                    const int k0 = p*16 + sub*8;
                    #pragma unroll
                    for (int mt = 0; mt < 2; ++mt) {
                        int r0 = (mg*32 + mt*16 + g)*PITCH_;
                        a[sub][mt][0]=Ts[r0            + k0 + c    ];
                        a[sub][mt][1]=Ts[r0 + 8*PITCH_ + k0 + c    ];
                        a[sub][mt][2]=Ts[r0            + k0 + c + 4];
                        a[sub][mt][3]=Ts[r0 + 8*PITCH_ + k0 + c + 4];
                    }
                }
                #pragma unroll
                for (int nt = 0; nt < 4; ++nt) {
                    uint4 B4 = __ldg(&W1p4[((ng*8 + p)*4 + nt)*32 + lane]);
                    uint32_t b0[2] = {B4.x, B4.y};
                    uint32_t b1f[2] = {B4.z, B4.w};
                    #pragma unroll
                    for (int mt = 0; mt < 2; ++mt) {
                        mma_tf32(acc[mt][nt], a[0][mt], b0);
                        mma_tf32(acc[mt][nt], a[1][mt], b1f);
                    }
                }
            }
            #pragma unroll
            for (int mt = 0; mt < 2; ++mt)
                #pragma unroll
                for (int nt = 0; nt < 4; ++nt)
                    #pragma unroll
                    for (int i = 0; i < 4; ++i) {
                        int row = mg*32 + mt*16 + g + ((i>>1)<<3);
                        int col = ng*32 + nt*8 + (c<<1) + (i&1);
                        float v = sspf(acc[mt][nt][i] + b1s[col]);
                        Hs[row*PITCH_ + col] = f2tf32(v);
                    }
        }
        __syncthreads();   // Hs ready; Ts fragment reads complete

        // ================= GEMM2: Wt = H @ W2 + b2  (-> Ts region) =================
        {
            float acc[2][4][4];
            #pragma unroll
            for (int mt=0;mt<2;mt++)
                #pragma unroll
                for (int nt=0;nt<4;nt++)
                    #pragma unroll
                    for (int i=0;i<4;i++) acc[mt][nt][i]=0.f;
            #pragma unroll
            for (int p = 0; p < 8; ++p) {
                uint32_t a[2][2][4];
                #pragma unroll
                for (int sub = 0; sub < 2; ++sub) {
                    const int k0 = p*16 + sub*8;
                    #pragma unroll
                    for (int mt = 0; mt < 2; ++mt) {
                        int r0 = (mg*32 + mt*16 + g)*PITCH_;
                        a[sub][mt][0]=Hs[r0            + k0 + c    ];
                        a[sub][mt][1]=Hs[r0 + 8*PITCH_ + k0 + c    ];
                        a[sub][mt][2]=Hs[r0            + k0 + c + 4];
                        a[sub][mt][3]=Hs[r0 + 8*PITCH_ + k0 + c + 4];
                    }
                }
                #pragma unroll
                for (int nt = 0; nt < 4; ++nt) {
                    uint4 B4 = __ldg(&W2p4[((ng*8 + p)*4 + nt)*32 + lane]);
                    uint32_t b0[2] = {B4.x, B4.y};
                    uint32_t b1f[2] = {B4.z, B4.w};
                    #pragma unroll
                    for (int mt = 0; mt < 2; ++mt) {
                        mma_tf32(acc[mt][nt], a[0][mt], b0);
                        mma_tf32(acc[mt][nt], a[1][mt], b1f);
                    }
                }
            }
            #pragma unroll
            for (int mt = 0; mt < 2; ++mt)
                #pragma unroll
                for (int nt = 0; nt < 4; ++nt)
                    #pragma unroll
                    for (int i = 0; i < 4; ++i) {
                        int row = mg*32 + mt*16 + g + ((i>>1)<<3);
                        int col = ng*32 + nt*8 + (c<<1) + (i&1);
                        Tf[row*PITCH_ + col] = acc[mt][nt][i] + b2s[col];
                    }
        }
        __syncthreads();   // Wt complete

        // ===== elementwise (vectorized): acc4 += m*yj4*yk4*wt4 =====
        #pragma unroll
        for (int i = 0; i < 8; ++i) {
            int r = rq*8 + i;
            int jrow = js[r], krow = ks[r];
            float m  = ms[r];
            float4 yj = *reinterpret_cast<const float4*>(&yb[jrow*NF_ + cg*4]);
            float4 yk = *reinterpret_cast<const float4*>(&yb[krow*NF_ + cg*4]);
            float4 wt = *reinterpret_cast<const float4*>(&Tf[r*PITCH_ + cg*4]);
            acc4.x = fmaf(m * yj.x * yk.x, wt.x, acc4.x);
            acc4.y = fmaf(m * yj.y * yk.y, wt.y, acc4.y);
            acc4.z = fmaf(m * yj.z * yk.z, wt.z, acc4.z);
            acc4.w = fmaf(m * yj.w * yk.w, wt.w, acc4.w);
        }
    }

    // ===== reduce acc4 across rq groups, then per-atom epilogue =====
    *reinterpret_cast<float4*>(&aggp[(rq*32 + cg)*4]) = acc4;
    __syncthreads();
    if (t < 128) {
        float s = 0.f;
        #pragma unroll
        for (int r = 0; r < 8; ++r) s += aggp[r*128 + t];
        aggs[t] = s;
    }
    __syncthreads();
    if (t < 128) {
        float a1 = bf2[t];
        #pragma unroll 8
        for (int gg = 0; gg < 128; ++gg)
            a1 = fmaf(aggs[gg], Wf2[gg*NB_ + t], a1);
        t1s[t] = sspf(a1);
    }
    __syncthreads();
    if (t < 128) {
        float a2 = bd[t];
        #pragma unroll 8
        for (int gg = 0; gg < 128; ++gg)
            a2 = fmaf(t1s[gg], Wd[gg*NB_ + t], a2);
        out[atom*NB_ + t] = x[atom*NB_ + t] + a2;
    }
}

// ---------------------------------------------------------------------------
extern "C" void kernel_launch(void* const* d_in, const int* in_sizes, int n_in,
                              void* d_out, int out_size)
{
    const float* x      = (const float*)d_in[0];
    const float* triple = (const float*)d_in[1];
    const int*   nj     = (const int*)  d_in[2];
    const int*   nk     = (const int*)  d_in[3];
    const float* mask   = (const float*)d_in[4];
    const float* W1     = (const float*)d_in[5];
    const float* b1     = (const float*)d_in[6];
    const float* W2     = (const float*)d_in[7];
    const float* b2     = (const float*)d_in[8];
    const float* Win    = (const float*)d_in[9];
    const float* Wf2    = (const float*)d_in[10];
    const float* bf2    = (const float*)d_in[11];
    const float* Wd     = (const float*)d_in[12];
    const float* bd     = (const float*)d_in[13];
    float* out = (float*)d_out;

    cudaFuncSetAttribute(fused_kernel,
                         cudaFuncAttributeMaxDynamicSharedMemorySize, SMEM_BYTES);

    prep_kernel<<<ATOMS_ + 64, 128>>>(x, Win, W1, W2);
    fused_kernel<<<ATOMS_, 256, SMEM_BYTES>>>(triple, nj, nk, mask,
                                              b1, b2, Wf2, bf2, Wd, bd, x, out);
}

// round 7
// speedup vs baseline: 2.1939x; 1.2184x over previous
#include <cuda_runtime.h>
#include <cuda_fp16.h>
#include <cstdint>

#define B_      8
#define AT_     96
#define NBR_    512
#define NANG_   125
#define NF_     128
#define NB_     128
#define ATOMS_  (B_*AT_)      // 768
#define CHUNK_  64
#define NCHUNK_ (NBR_/CHUNK_) // 8
#define PITCH_  132           // f32 Wt tile pitch (%32==4, %4==0)
#define PH_     68            // half2-word pitch for T16/H16 (%32==4)

// smem layout (u32 units)
#define SM_T    0                       // T16 (64xPH_=4352) then Wt f32 (64x132=8448)
#define SM_H    8448                    // H16 (4352)
#define SM_EX   12800
// EX floats: b1s[128] b2s[128] js[64] ks[64] ms[64] aggp[1024] aggs[128] t1s[128] = 1728
#define SMEM_U32   (SM_EX + 1728)
#define SMEM_BYTES (SMEM_U32*4)         // 58,112 B -> 3 CTAs/SM

__device__ float g_y[ATOMS_ * NF_];                 // y = x @ Win
// packed fp16 B fragments: uint4 idx = ((ng*8+p)*2+ntp)*32+lane
//   x = {W[k0][n0],W[k0+1][n0]}  y = {W[k0+8][n0],W[k0+9][n0]}
//   z,w = same at n1=n0+8;  k0=16p+2c, n0=ng*32+ntp*16+g  (lane=g*4+c)
__device__ __align__(16) uint32_t g_W1p[2048*4];
__device__ __align__(16) uint32_t g_W2p[2048*4];

__device__ __forceinline__ float sspf(float x) {
    return fmaxf(x, 0.f) + __logf(1.f + __expf(-fabsf(x))) - 0.6931471805599453f;
}
__device__ __forceinline__ uint32_t packh2(float lo, float hi) {
    __half2 h = __halves2half2(__float2half_rn(lo), __float2half_rn(hi));
    return *reinterpret_cast<uint32_t*>(&h);
}
__device__ __forceinline__ void mma_f16(float c[4], const uint32_t a[4], const uint32_t b[2]) {
    asm volatile(
        "mma.sync.aligned.m16n8k16.row.col.f32.f16.f16.f32 "
        "{%0,%1,%2,%3}, {%4,%5,%6,%7}, {%8,%9}, {%0,%1,%2,%3};"
        : "+f"(c[0]), "+f"(c[1]), "+f"(c[2]), "+f"(c[3])
        : "r"(a[0]), "r"(a[1]), "r"(a[2]), "r"(a[3]), "r"(b[0]), "r"(b[1]));
}

// ---------------------------------------------------------------------------
// Prep: y = x@Win (blocks 0..767); fp16 B-fragment packing (blocks 768..799)
// ---------------------------------------------------------------------------
__global__ void __launch_bounds__(128)
prep_kernel(const float* __restrict__ x, const float* __restrict__ Win,
            const float* __restrict__ W1, const float* __restrict__ W2)
{
    const int bid = blockIdx.x, t = threadIdx.x;
    if (bid < ATOMS_) {
        __shared__ float xs[NB_];
        xs[t] = x[bid*NB_ + t];
        __syncthreads();
        float acc = 0.f;
        #pragma unroll 16
        for (int gg = 0; gg < NB_; ++gg)
            acc = fmaf(xs[gg], Win[gg*NF_ + t], acc);
        g_y[bid*NF_ + t] = acc;
    } else {
        int e = (bid - ATOMS_)*128 + t;          // 0..4095
        const float* W   = (e < 2048) ? W1 : W2;
        const int   kmax = (e < 2048) ? NANG_ : 128;
        uint32_t*   dst  = (e < 2048) ? g_W1p : g_W2p;
        int e2 = e & 2047;
        int lane = e2 & 31, ntp = (e2>>5)&1, p = (e2>>6)&7, ng = e2>>9;
        int g = lane>>2, c = lane&3;
        int n0 = ng*32 + ntp*16 + g;
        int n1 = n0 + 8;
        int k0 = 16*p + 2*c;
        auto rd = [&](int k, int n) -> float {
            return (k < kmax) ? W[k*128 + n] : 0.f;
        };
        uint4 v;
        v.x = packh2(rd(k0,   n0), rd(k0+1, n0));
        v.y = packh2(rd(k0+8, n0), rd(k0+9, n0));
        v.z = packh2(rd(k0,   n1), rd(k0+1, n1));
        v.w = packh2(rd(k0+8, n1), rd(k0+9, n1));
        reinterpret_cast<uint4*>(dst)[e2] = v;
    }
}

// ---------------------------------------------------------------------------
// Fused main kernel: one CTA per atom, fp16 MMA, 3 CTAs/SM
// ---------------------------------------------------------------------------
__global__ void __launch_bounds__(256, 3)
fused_kernel(const float* __restrict__ triple,
             const int*   __restrict__ nj, const int* __restrict__ nk,
             const float* __restrict__ mask,
             const float* __restrict__ b1, const float* __restrict__ b2,
             const float* __restrict__ Wf2, const float* __restrict__ bf2,
             const float* __restrict__ Wd,  const float* __restrict__ bd,
             const float* __restrict__ x,   float* __restrict__ out)
{
    extern __shared__ uint32_t sm[];
    uint32_t* T16 = sm + SM_T;                      // half2 words, 64 x PH_
    float*    Tf  = reinterpret_cast<float*>(sm + SM_T);   // Wt f32 view (64 x PITCH_)
    uint32_t* H16 = sm + SM_H;                      // half2 words, 64 x PH_
    float*    ex  = reinterpret_cast<float*>(sm + SM_EX);
    float* b1s = ex;
    float* b2s = ex + 128;
    int*   js  = reinterpret_cast<int*>(ex + 256);
    int*   ks  = js + 64;
    float* ms  = ex + 256 + 128;
    float* aggp = ms + 64;                // 1024
    float* aggs = aggp + 1024;            // 128
    float* t1s  = aggs + 128;             // 128

    const int t    = threadIdx.x;
    const int atom = blockIdx.x;
    const int bidx = atom / AT_;
    const int lane = t & 31;
    const int warp = t >> 5;
    const int g  = lane >> 2;
    const int c  = lane & 3;
    const int mg = warp >> 2;      // 0..1
    const int ng = warp & 3;       // 0..3

    if (t < 128) { b1s[t] = b1[t]; b2s[t] = b2[t]; }

    const int nb = atom * NBR_;
    const float* yb = g_y + bidx * AT_ * NF_;
    const uint4* W1p4 = reinterpret_cast<const uint4*>(g_W1p);
    const uint4* W2p4 = reinterpret_cast<const uint4*>(g_W2p);

    const int cg = t & 31;
    const int rq = t >> 5;
    float4 acc4 = make_float4(0.f, 0.f, 0.f, 0.f);

    for (int ch = 0; ch < NCHUNK_; ++ch) {
        __syncthreads();   // prev EW done with Tf before T16 overwrite

        // ---- T scatter (fp16): warp w -> rows w*8..w*8+7 ----
        {
            const float* tbase = triple + ((size_t)nb + (size_t)ch*CHUNK_ + warp*8)*NANG_;
            #pragma unroll
            for (int i = 0; i < 8; ++i) {
                const float* trow = tbase + i*NANG_;
                uint32_t* srow = &T16[(warp*8 + i)*PH_];
                #pragma unroll
                for (int q = 0; q < 2; ++q) {
                    int k0 = 2*lane + 64*q;
                    float v0 = (k0     < NANG_) ? __ldg(trow + k0)     : 0.f;
                    float v1 = (k0 + 1 < NANG_) ? __ldg(trow + k0 + 1) : 0.f;
                    srow[lane + 32*q] = packh2(v0, v1);
                }
            }
        }
        if (t < CHUNK_) {
            js[t] = nj[nb + ch*CHUNK_ + t];
            ks[t] = nk[nb + ch*CHUNK_ + t];
            ms[t] = mask[nb + ch*CHUNK_ + t];
        }
        __syncthreads();

        // ================= GEMM1: H = ssp(T @ W1 + b1)  [fp16 k16] =================
        {
            float acc[2][4][4];
            #pragma unroll
            for (int mt=0;mt<2;mt++)
                #pragma unroll
                for (int nt=0;nt<4;nt++)
                    #pragma unroll
                    for (int i=0;i<4;i++) acc[mt][nt][i]=0.f;
            #pragma unroll
            for (int p = 0; p < 8; ++p) {      // k = 16p..16p+15
                uint32_t a[2][4];
                #pragma unroll
                for (int mt = 0; mt < 2; ++mt) {
                    int r0 = (mg*32 + mt*16 + g)*PH_ + p*8;
                    a[mt][0]=T16[r0          + c    ];
                    a[mt][1]=T16[r0 + 8*PH_  + c    ];
                    a[mt][2]=T16[r0          + c + 4];
                    a[mt][3]=T16[r0 + 8*PH_  + c + 4];
                }
                #pragma unroll
                for (int ntp = 0; ntp < 2; ++ntp) {
                    uint4 B4 = __ldg(&W1p4[((ng*8 + p)*2 + ntp)*32 + lane]);
                    uint32_t bb0[2] = {B4.x, B4.y};
                    uint32_t bb1[2] = {B4.z, B4.w};
                    #pragma unroll
                    for (int mt = 0; mt < 2; ++mt) {
                        mma_f16(acc[mt][ntp*2    ], a[mt], bb0);
                        mma_f16(acc[mt][ntp*2 + 1], a[mt], bb1);
                    }
                }
            }
            // epilogue: ssp -> half2 -> H16
            #pragma unroll
            for (int mt = 0; mt < 2; ++mt)
                #pragma unroll
                for (int nt = 0; nt < 4; ++nt) {
                    int col0 = ng*32 + nt*8 + 2*c;
                    int w0   = ng*16 + nt*4 + c;   // half2 word index
                    int rA = mg*32 + mt*16 + g;
                    float v0 = sspf(acc[mt][nt][0] + b1s[col0]);
                    float v1 = sspf(acc[mt][nt][1] + b1s[col0+1]);
                    H16[rA*PH_ + w0] = packh2(v0, v1);
                    float v2 = sspf(acc[mt][nt][2] + b1s[col0]);
                    float v3 = sspf(acc[mt][nt][3] + b1s[col0+1]);
                    H16[(rA+8)*PH_ + w0] = packh2(v2, v3);
                }
        }
        __syncthreads();   // H ready; T16 reads complete -> Tf region reusable

        // ================= GEMM2: Wt = H @ W2 + b2  (-> Tf f32) =================
        {
            float acc[2][4][4];
            #pragma unroll
            for (int mt=0;mt<2;mt++)
                #pragma unroll
                for (int nt=0;nt<4;nt++)
                    #pragma unroll
                    for (int i=0;i<4;i++) acc[mt][nt][i]=0.f;
            #pragma unroll
            for (int p = 0; p < 8; ++p) {
                uint32_t a[2][4];
                #pragma unroll
                for (int mt = 0; mt < 2; ++mt) {
                    int r0 = (mg*32 + mt*16 + g)*PH_ + p*8;
                    a[mt][0]=H16[r0          + c    ];
                    a[mt][1]=H16[r0 + 8*PH_  + c    ];
                    a[mt][2]=H16[r0          + c + 4];
                    a[mt][3]=H16[r0 + 8*PH_  + c + 4];
                }
                #pragma unroll
                for (int ntp = 0; ntp < 2; ++ntp) {
                    uint4 B4 = __ldg(&W2p4[((ng*8 + p)*2 + ntp)*32 + lane]);
                    uint32_t bb0[2] = {B4.x, B4.y};
                    uint32_t bb1[2] = {B4.z, B4.w};
                    #pragma unroll
                    for (int mt = 0; mt < 2; ++mt) {
                        mma_f16(acc[mt][ntp*2    ], a[mt], bb0);
                        mma_f16(acc[mt][ntp*2 + 1], a[mt], bb1);
                    }
                }
            }
            #pragma unroll
            for (int mt = 0; mt < 2; ++mt)
                #pragma unroll
                for (int nt = 0; nt < 4; ++nt) {
                    int col0 = ng*32 + nt*8 + 2*c;
                    int rA = mg*32 + mt*16 + g;
                    Tf[rA*PITCH_     + col0  ] = acc[mt][nt][0] + b2s[col0];
                    Tf[rA*PITCH_     + col0+1] = acc[mt][nt][1] + b2s[col0+1];
                    Tf[(rA+8)*PITCH_ + col0  ] = acc[mt][nt][2] + b2s[col0];
                    Tf[(rA+8)*PITCH_ + col0+1] = acc[mt][nt][3] + b2s[col0+1];
                }
        }
        __syncthreads();   // Wt complete

        // ===== elementwise (vectorized): acc4 += m*yj4*yk4*wt4 =====
        #pragma unroll
        for (int i = 0; i < 8; ++i) {
            int r = rq*8 + i;
            int jrow = js[r], krow = ks[r];
            float m  = ms[r];
            float4 yj = *reinterpret_cast<const float4*>(&yb[jrow*NF_ + cg*4]);
            float4 yk = *reinterpret_cast<const float4*>(&yb[krow*NF_ + cg*4]);
            float4 wt = *reinterpret_cast<const float4*>(&Tf[r*PITCH_ + cg*4]);
            acc4.x = fmaf(m * yj.x * yk.x, wt.x, acc4.x);
            acc4.y = fmaf(m * yj.y * yk.y, wt.y, acc4.y);
            acc4.z = fmaf(m * yj.z * yk.z, wt.z, acc4.z);
            acc4.w = fmaf(m * yj.w * yk.w, wt.w, acc4.w);
        }
    }

    // ===== reduce acc4 across rq groups, then per-atom epilogue =====
    *reinterpret_cast<float4*>(&aggp[(rq*32 + cg)*4]) = acc4;
    __syncthreads();
    if (t < 128) {
        float s = 0.f;
        #pragma unroll
        for (int r = 0; r < 8; ++r) s += aggp[r*128 + t];
        aggs[t] = s;
    }
    __syncthreads();
    if (t < 128) {
        float a1 = bf2[t];
        #pragma unroll 8
        for (int gg = 0; gg < 128; ++gg)
            a1 = fmaf(aggs[gg], Wf2[gg*NB_ + t], a1);
        t1s[t] = sspf(a1);
    }
    __syncthreads();
    if (t < 128) {
        float a2 = bd[t];
        #pragma unroll 8
        for (int gg = 0; gg < 128; ++gg)
            a2 = fmaf(t1s[gg], Wd[gg*NB_ + t], a2);
        out[atom*NB_ + t] = x[atom*NB_ + t] + a2;
    }
}

// ---------------------------------------------------------------------------
extern "C" void kernel_launch(void* const* d_in, const int* in_sizes, int n_in,
                              void* d_out, int out_size)
{
    const float* x      = (const float*)d_in[0];
    const float* triple = (const float*)d_in[1];
    const int*   nj     = (const int*)  d_in[2];
    const int*   nk     = (const int*)  d_in[3];
    const float* mask   = (const float*)d_in[4];
    const float* W1     = (const float*)d_in[5];
    const float* b1     = (const float*)d_in[6];
    const float* W2     = (const float*)d_in[7];
    const float* b2     = (const float*)d_in[8];
    const float* Win    = (const float*)d_in[9];
    const float* Wf2    = (const float*)d_in[10];
    const float* bf2    = (const float*)d_in[11];
    const float* Wd     = (const float*)d_in[12];
    const float* bd     = (const float*)d_in[13];
    float* out = (float*)d_out;

    cudaFuncSetAttribute(fused_kernel,
                         cudaFuncAttributeMaxDynamicSharedMemorySize, SMEM_BYTES);

    prep_kernel<<<ATOMS_ + 32, 128>>>(x, Win, W1, W2);
    fused_kernel<<<ATOMS_, 256, SMEM_BYTES>>>(triple, nj, nk, mask,
                                              b1, b2, Wf2, bf2, Wd, bd, x, out);
}

// round 8
// speedup vs baseline: 2.3640x; 1.0775x over previous
#include <cuda_runtime.h>
#include <cuda_fp16.h>
#include <cstdint>

#define B_      8
#define AT_     96
#define NBR_    512
#define NANG_   125
#define NF_     128
#define NB_     128
#define ATOMS_  (B_*AT_)      // 768
#define CHUNK_  64
#define NCHUNK_ (NBR_/CHUNK_) // 8
#define PH_     68            // half2-word pitch (%32==4 -> conflict-free)

// smem layout (u32 units)
#define SM_TA   0              // T16 buffer A (64 x PH_ = 4352)
#define SM_TB   4352           // T16 buffer B
#define SM_H    8704           // H16
#define SM_W    13056          // W16 (Wt as half2, mask folded)
#define SM_EX   17408
// EX floats: b1s[128] b2s[128] js2[128] ks2[128] ms2[128] = 640
#define SMEM_U32   (SM_EX + 640)
#define SMEM_BYTES (SMEM_U32*4)   // 72,192 B -> 3 CTAs/SM (216.6KB)

__device__ float g_y[ATOMS_ * NF_];                 // y = x @ Win
// packed fp16 B fragments: uint4 idx = ((ng*8+p)*2+ntp)*32+lane
__device__ __align__(16) uint32_t g_W1p[2048*4];
__device__ __align__(16) uint32_t g_W2p[2048*4];

__device__ __forceinline__ float sspf(float x) {
    return fmaxf(x, 0.f) + __logf(1.f + __expf(-fabsf(x))) - 0.6931471805599453f;
}
__device__ __forceinline__ uint32_t packh2(float lo, float hi) {
    __half2 h = __halves2half2(__float2half_rn(lo), __float2half_rn(hi));
    return *reinterpret_cast<uint32_t*>(&h);
}
__device__ __forceinline__ float2 h2tof2(uint32_t u) {
    __half2 h = *reinterpret_cast<__half2*>(&u);
    return __half22float2(h);
}
__device__ __forceinline__ void mma_f16(float c[4], const uint32_t a[4], const uint32_t b[2]) {
    asm volatile(
        "mma.sync.aligned.m16n8k16.row.col.f32.f16.f16.f32 "
        "{%0,%1,%2,%3}, {%4,%5,%6,%7}, {%8,%9}, {%0,%1,%2,%3};"
        : "+f"(c[0]), "+f"(c[1]), "+f"(c[2]), "+f"(c[3])
        : "r"(a[0]), "r"(a[1]), "r"(a[2]), "r"(a[3]), "r"(b[0]), "r"(b[1]));
}

// ---------------------------------------------------------------------------
// Prep: y = x@Win (blocks 0..767); fp16 B-fragment packing (blocks 768..799)
// ---------------------------------------------------------------------------
__global__ void __launch_bounds__(128)
prep_kernel(const float* __restrict__ x, const float* __restrict__ Win,
            const float* __restrict__ W1, const float* __restrict__ W2)
{
    const int bid = blockIdx.x, t = threadIdx.x;
    if (bid < ATOMS_) {
        __shared__ float xs[NB_];
        xs[t] = x[bid*NB_ + t];
        __syncthreads();
        float acc = 0.f;
        #pragma unroll 16
        for (int gg = 0; gg < NB_; ++gg)
            acc = fmaf(xs[gg], Win[gg*NF_ + t], acc);
        g_y[bid*NF_ + t] = acc;
    } else {
        int e = (bid - ATOMS_)*128 + t;          // 0..4095
        const float* W   = (e < 2048) ? W1 : W2;
        const int   kmax = (e < 2048) ? NANG_ : 128;
        uint32_t*   dst  = (e < 2048) ? g_W1p : g_W2p;
        int e2 = e & 2047;
        int lane = e2 & 31, ntp = (e2>>5)&1, p = (e2>>6)&7, ng = e2>>9;
        int g = lane>>2, c = lane&3;
        int n0 = ng*32 + ntp*16 + g;
        int n1 = n0 + 8;
        int k0 = 16*p + 2*c;
        auto rd = [&](int k, int n) -> float {
            return (k < kmax) ? W[k*128 + n] : 0.f;
        };
        uint4 v;
        v.x = packh2(rd(k0,   n0), rd(k0+1, n0));
        v.y = packh2(rd(k0+8, n0), rd(k0+9, n0));
        v.z = packh2(rd(k0,   n1), rd(k0+1, n1));
        v.w = packh2(rd(k0+8, n1), rd(k0+9, n1));
        reinterpret_cast<uint4*>(dst)[e2] = v;
    }
}

// ---------------------------------------------------------------------------
// Fused main kernel: pipelined, 2 barriers/chunk, 3 CTAs/SM
// ---------------------------------------------------------------------------
__global__ void __launch_bounds__(256, 3)
fused_kernel(const float* __restrict__ triple,
             const int*   __restrict__ nj, const int* __restrict__ nk,
             const float* __restrict__ mask,
             const float* __restrict__ b1, const float* __restrict__ b2,
             const float* __restrict__ Wf2, const float* __restrict__ bf2,
             const float* __restrict__ Wd,  const float* __restrict__ bd,
             const float* __restrict__ x,   float* __restrict__ out)
{
    extern __shared__ uint32_t sm[];
    uint32_t* TA  = sm + SM_TA;
    uint32_t* TB  = sm + SM_TB;
    uint32_t* H16 = sm + SM_H;
    uint32_t* W16 = sm + SM_W;
    float*    ex  = reinterpret_cast<float*>(sm + SM_EX);
    float* b1s = ex;
    float* b2s = ex + 128;
    int*   js2 = reinterpret_cast<int*>(ex + 256);   // [2][64]
    int*   ks2 = reinterpret_cast<int*>(ex + 384);   // [2][64]
    float* ms2 = ex + 512;                           // [2][64]
    // post-loop scratch aliases the T buffers (loop done by then)
    float* aggp = reinterpret_cast<float*>(sm);      // 1024
    float* aggs = aggp + 1024;                       // 128
    float* t1s  = aggs + 128;                        // 128

    const int t    = threadIdx.x;
    const int atom = blockIdx.x;
    const int bidx = atom / AT_;
    const int lane = t & 31;
    const int warp = t >> 5;
    const int g  = lane >> 2;
    const int c  = lane & 3;
    const int mg = warp >> 2;      // 0..1
    const int ng = warp & 3;       // 0..3

    if (t < 128) { b1s[t] = b1[t]; b2s[t] = b2[t]; }

    const int nb = atom * NBR_;
    const float* yb = g_y + bidx * AT_ * NF_;
    const uint4* W1p4 = reinterpret_cast<const uint4*>(g_W1p);
    const uint4* W2p4 = reinterpret_cast<const uint4*>(g_W2p);

    const int cg = t & 31;
    const int rq = t >> 5;
    float4 acc4 = make_float4(0.f, 0.f, 0.f, 0.f);

    // ---- scatter lambda: chunk ch -> buffer buf ----
    auto scatter = [&](int ch, uint32_t* Tb, int buf) {
        const float* tbase = triple + ((size_t)nb + (size_t)ch*CHUNK_ + warp*8)*NANG_;
        #pragma unroll
        for (int i = 0; i < 8; ++i) {
            const float* trow = tbase + i*NANG_;
            uint32_t* srow = &Tb[(warp*8 + i)*PH_];
            #pragma unroll
            for (int q = 0; q < 2; ++q) {
                int k0 = 2*lane + 64*q;
                float v0 = (k0     < NANG_) ? __ldg(trow + k0)     : 0.f;
                float v1 = (k0 + 1 < NANG_) ? __ldg(trow + k0 + 1) : 0.f;
                srow[lane + 32*q] = packh2(v0, v1);
            }
        }
        if (t < CHUNK_) {
            js2[buf*64 + t] = nj[nb + ch*CHUNK_ + t];
            ks2[buf*64 + t] = nk[nb + ch*CHUNK_ + t];
            ms2[buf*64 + t] = mask[nb + ch*CHUNK_ + t];
        }
    };

    // prologue: chunk 0 into buffer A
    scatter(0, TA, 0);
    __syncthreads();

    for (int ch = 0; ch < NCHUNK_; ++ch) {
        const int cur = ch & 1;
        uint32_t* Tc = cur ? TB : TA;
        uint32_t* Tn = cur ? TA : TB;

        // ================= GEMM1: H = ssp(T @ W1 + b1) =================
        {
            float acc[2][4][4];
            #pragma unroll
            for (int mt=0;mt<2;mt++)
                #pragma unroll
                for (int nt=0;nt<4;nt++)
                    #pragma unroll
                    for (int i=0;i<4;i++) acc[mt][nt][i]=0.f;
            #pragma unroll
            for (int p = 0; p < 8; ++p) {
                uint32_t a[2][4];
                #pragma unroll
                for (int mt = 0; mt < 2; ++mt) {
                    int r0 = (mg*32 + mt*16 + g)*PH_ + p*8;
                    a[mt][0]=Tc[r0          + c    ];
                    a[mt][1]=Tc[r0 + 8*PH_  + c    ];
                    a[mt][2]=Tc[r0          + c + 4];
                    a[mt][3]=Tc[r0 + 8*PH_  + c + 4];
                }
                #pragma unroll
                for (int ntp = 0; ntp < 2; ++ntp) {
                    uint4 B4 = __ldg(&W1p4[((ng*8 + p)*2 + ntp)*32 + lane]);
                    uint32_t bb0[2] = {B4.x, B4.y};
                    uint32_t bb1[2] = {B4.z, B4.w};
                    #pragma unroll
                    for (int mt = 0; mt < 2; ++mt) {
                        mma_f16(acc[mt][ntp*2    ], a[mt], bb0);
                        mma_f16(acc[mt][ntp*2 + 1], a[mt], bb1);
                    }
                }
            }
            #pragma unroll
            for (int mt = 0; mt < 2; ++mt)
                #pragma unroll
                for (int nt = 0; nt < 4; ++nt) {
                    int col0 = ng*32 + nt*8 + 2*c;
                    int w0   = ng*16 + nt*4 + c;
                    int rA = mg*32 + mt*16 + g;
                    H16[rA*PH_ + w0] =
                        packh2(sspf(acc[mt][nt][0] + b1s[col0]),
                               sspf(acc[mt][nt][1] + b1s[col0+1]));
                    H16[(rA+8)*PH_ + w0] =
                        packh2(sspf(acc[mt][nt][2] + b1s[col0]),
                               sspf(acc[mt][nt][3] + b1s[col0+1]));
                }
        }
        __syncthreads();   // H ready; Tc reads done

        // ---- pipelined scatter of next chunk (overlaps GEMM2 issue) ----
        if (ch + 1 < NCHUNK_)
            scatter(ch + 1, Tn, cur ^ 1);

        // ================= GEMM2: W16 = (H @ W2 + b2) * m  [fp16 out] =================
        {
            float acc[2][4][4];
            #pragma unroll
            for (int mt=0;mt<2;mt++)
                #pragma unroll
                for (int nt=0;nt<4;nt++)
                    #pragma unroll
                    for (int i=0;i<4;i++) acc[mt][nt][i]=0.f;
            #pragma unroll
            for (int p = 0; p < 8; ++p) {
                uint32_t a[2][4];
                #pragma unroll
                for (int mt = 0; mt < 2; ++mt) {
                    int r0 = (mg*32 + mt*16 + g)*PH_ + p*8;
                    a[mt][0]=H16[r0          + c    ];
                    a[mt][1]=H16[r0 + 8*PH_  + c    ];
                    a[mt][2]=H16[r0          + c + 4];
                    a[mt][3]=H16[r0 + 8*PH_  + c + 4];
                }
                #pragma unroll
                for (int ntp = 0; ntp < 2; ++ntp) {
                    uint4 B4 = __ldg(&W2p4[((ng*8 + p)*2 + ntp)*32 + lane]);
                    uint32_t bb0[2] = {B4.x, B4.y};
                    uint32_t bb1[2] = {B4.z, B4.w};
                    #pragma unroll
                    for (int mt = 0; mt < 2; ++mt) {
                        mma_f16(acc[mt][ntp*2    ], a[mt], bb0);
                        mma_f16(acc[mt][ntp*2 + 1], a[mt], bb1);
                    }
                }
            }
            #pragma unroll
            for (int mt = 0; mt < 2; ++mt) {
                int rA = mg*32 + mt*16 + g;
                float mA = ms2[cur*64 + rA];
                float mB = ms2[cur*64 + rA + 8];
                #pragma unroll
                for (int nt = 0; nt < 4; ++nt) {
                    int col0 = ng*32 + nt*8 + 2*c;
                    int w0   = ng*16 + nt*4 + c;
                    W16[rA*PH_ + w0] =
                        packh2((acc[mt][nt][0] + b2s[col0])  * mA,
                               (acc[mt][nt][1] + b2s[col0+1])* mA);
                    W16[(rA+8)*PH_ + w0] =
                        packh2((acc[mt][nt][2] + b2s[col0])  * mB,
                               (acc[mt][nt][3] + b2s[col0+1])* mB);
                }
            }
        }
        __syncthreads();   // W16 ready; Tn writes complete

        // ===== elementwise: acc4 += yj4*yk4*wt4 (mask folded into wt) =====
        #pragma unroll
        for (int i = 0; i < 8; ++i) {
            int r = rq*8 + i;
            int jrow = js2[cur*64 + r], krow = ks2[cur*64 + r];
            float4 yj = *reinterpret_cast<const float4*>(&yb[jrow*NF_ + cg*4]);
            float4 yk = *reinterpret_cast<const float4*>(&yb[krow*NF_ + cg*4]);
            uint2 ww = *reinterpret_cast<const uint2*>(&W16[r*PH_ + cg*2]);
            float2 wa = h2tof2(ww.x);
            float2 wb = h2tof2(ww.y);
            acc4.x = fmaf(yj.x * yk.x, wa.x, acc4.x);
            acc4.y = fmaf(yj.y * yk.y, wa.y, acc4.y);
            acc4.z = fmaf(yj.z * yk.z, wb.x, acc4.z);
            acc4.w = fmaf(yj.w * yk.w, wb.y, acc4.w);
        }
        // no barrier: next GEMM1 reads Tn (disjoint); W16 next written after a sync
    }

    // ===== reduce acc4 across rq groups, then per-atom epilogue =====
    __syncthreads();   // all EW done before aliasing T buffers with aggp
    *reinterpret_cast<float4*>(&aggp[(rq*32 + cg)*4]) = acc4;
    __syncthreads();
    if (t < 128) {
        float s = 0.f;
        #pragma unroll
        for (int r = 0; r < 8; ++r) s += aggp[r*128 + t];
        aggs[t] = s;
    }
    __syncthreads();
    if (t < 128) {
        float a1 = bf2[t];
        #pragma unroll 8
        for (int gg = 0; gg < 128; ++gg)
            a1 = fmaf(aggs[gg], Wf2[gg*NB_ + t], a1);
        t1s[t] = sspf(a1);
    }
    __syncthreads();
    if (t < 128) {
        float a2 = bd[t];
        #pragma unroll 8
        for (int gg = 0; gg < 128; ++gg)
            a2 = fmaf(t1s[gg], Wd[gg*NB_ + t], a2);
        out[atom*NB_ + t] = x[atom*NB_ + t] + a2;
    }
}

// ---------------------------------------------------------------------------
extern "C" void kernel_launch(void* const* d_in, const int* in_sizes, int n_in,
                              void* d_out, int out_size)
{
    const float* x      = (const float*)d_in[0];
    const float* triple = (const float*)d_in[1];
    const int*   nj     = (const int*)  d_in[2];
    const int*   nk     = (const int*)  d_in[3];
    const float* mask   = (const float*)d_in[4];
    const float* W1     = (const float*)d_in[5];
    const float* b1     = (const float*)d_in[6];
    const float* W2     = (const float*)d_in[7];
    const float* b2     = (const float*)d_in[8];
    const float* Win    = (const float*)d_in[9];
    const float* Wf2    = (const float*)d_in[10];
    const float* bf2    = (const float*)d_in[11];
    const float* Wd     = (const float*)d_in[12];
    const float* bd     = (const float*)d_in[13];
    float* out = (float*)d_out;

    cudaFuncSetAttribute(fused_kernel,
                         cudaFuncAttributeMaxDynamicSharedMemorySize, SMEM_BYTES);

    prep_kernel<<<ATOMS_ + 32, 128>>>(x, Win, W1, W2);
    fused_kernel<<<ATOMS_, 256, SMEM_BYTES>>>(triple, nj, nk, mask,
                                              b1, b2, Wf2, bf2, Wd, bd, x, out);
}